// round 15
// baseline (speedup 1.0000x reference)
#include <cuda_runtime.h>
#include <cuda_fp16.h>
#include <math.h>

#define N_NODES   20000
#define N_EDGES   320000
#define IN_DIM    128
#define HID       64
#define HEADS     4
#define NUM_GRAPHS 128
#define N_CLASSES 10
#define F1        (HID*HEADS)   // 256
#define MAXDEG    64

typedef unsigned long long ull;

// ---- scratch ----
__device__ __half g_ft1h[N_NODES * F1];
__device__ __half g_x1h [N_NODES * F1];
__device__ __half g_ft2h[N_NODES * HID];
__device__ int    g_cursor[N_NODES];
__device__ int    g_pad[N_NODES * MAXDEG];
__device__ float  g_pool[NUM_GRAPHS * HID];
__device__ float  g_pcnt[NUM_GRAPHS];

__global__ void zero_kernel() {
    int i = blockIdx.x * blockDim.x + threadIdx.x;
    if (i < N_NODES) g_cursor[i] = 0;
    if (i < NUM_GRAPHS * HID) g_pool[i] = 0.f;
    if (i < NUM_GRAPHS) g_pcnt[i] = 0.f;
}

__global__ void scatter_kernel(const int* __restrict__ src, const int* __restrict__ dst) {
    int i = blockIdx.x * blockDim.x + threadIdx.x;
    if (i < N_EDGES / 4) {
        int4 d = ((const int4*)dst)[i];
        int4 s = ((const int4*)src)[i];
        int p0 = atomicAdd(&g_cursor[d.x], 1);
        int p1 = atomicAdd(&g_cursor[d.y], 1);
        int p2 = atomicAdd(&g_cursor[d.z], 1);
        int p3 = atomicAdd(&g_cursor[d.w], 1);
        if (p0 < MAXDEG) g_pad[d.x * MAXDEG + p0] = s.x;
        if (p1 < MAXDEG) g_pad[d.y * MAXDEG + p1] = s.y;
        if (p2 < MAXDEG) g_pad[d.z * MAXDEG + p2] = s.z;
        if (p3 < MAXDEG) g_pad[d.w * MAXDEG + p3] = s.w;
    }
}

// ---- packed f32x2 helpers ----
__device__ __forceinline__ ull f2x_mul(ull a, ull b) {
    ull r; asm("mul.rn.f32x2 %0, %1, %2;" : "=l"(r) : "l"(a), "l"(b)); return r;
}
__device__ __forceinline__ ull f2x_fma(ull a, ull b, ull c) {
    ull r; asm("fma.rn.f32x2 %0, %1, %2, %3;" : "=l"(r) : "l"(a), "l"(b), "l"(c)); return r;
}
__device__ __forceinline__ ull f2x_pack(float lo, float hi) {
    ull r; asm("mov.b64 %0, {%1, %2};" : "=l"(r) : "f"(lo), "f"(hi)); return r;
}
__device__ __forceinline__ float2 f2x_unpack(ull v) {
    float2 t; asm("mov.b64 {%0, %1}, %2;" : "=f"(t.x), "=f"(t.y) : "l"(v)); return t;
}
__device__ __forceinline__ float f2x_dot8(const ull* a, const ull* b) {
    ull s = f2x_mul(a[0], b[0]);
    s = f2x_fma(a[1], b[1], s);
    s = f2x_fma(a[2], b[2], s);
    s = f2x_fma(a[3], b[3], s);
    float2 t = f2x_unpack(s);
    return t.x + t.y;
}
__device__ __forceinline__ void h8_to_p4(uint4 raw, ull* p) {
    __half2* hp = (__half2*)&raw;
#pragma unroll
    for (int j = 0; j < 4; j++) {
        float2 t = __half22float2(hp[j]);
        p[j] = f2x_pack(t.x, t.y);
    }
}

// ========================= TF32 GEMM helpers =========================
__device__ __forceinline__ unsigned f2tf32(float x) {
    unsigned r;
    asm("cvt.rna.tf32.f32 %0, %1;" : "=r"(r) : "f"(x));
    return r;
}

__device__ __forceinline__ void mma_tf32(float c[4],
                                         unsigned a0, unsigned a1, unsigned a2, unsigned a3,
                                         unsigned b0, unsigned b1) {
    asm volatile(
        "mma.sync.aligned.m16n8k8.row.col.f32.tf32.tf32.f32 "
        "{%0,%1,%2,%3}, {%4,%5,%6,%7}, {%8,%9}, {%0,%1,%2,%3};\n"
        : "+f"(c[0]), "+f"(c[1]), "+f"(c[2]), "+f"(c[3])
        : "r"(a0), "r"(a1), "r"(a2), "r"(a3), "r"(b0), "r"(b1));
}

#define GBM 128
#define GBN 64
#define GBK 16
#define ASTRIDE 20
#define BSTRIDE 72

// ---- GEMM A: 128x64 tile, 256 threads, fp32 A, half C (layer 1) ----
__global__ __launch_bounds__(256) void gemm_tf32_kernel(
    const float* __restrict__ A, const float* __restrict__ B,
    __half* __restrict__ C, int M, int N, int K) {
    __shared__ unsigned As[GBM][ASTRIDE];
    __shared__ unsigned Bs[GBK][BSTRIDE];

    int t = threadIdx.x;
    int lane = t & 31;
    int warp = t >> 5;
    int wm = (warp >> 1) * 32;
    int wn = (warp & 1) * 32;
    int bm = blockIdx.y * GBM;
    int bn = blockIdx.x * GBN;

    int lr = lane >> 2;
    int lc = lane & 3;

    float acc[2][4][4];
#pragma unroll
    for (int mt = 0; mt < 2; mt++)
#pragma unroll
        for (int nt = 0; nt < 4; nt++)
#pragma unroll
            for (int i = 0; i < 4; i++) acc[mt][nt][i] = 0.f;

    int a_row = t >> 2;
    int a_col = (t & 3) * 4;
    int b_row = t >> 4;
    int b_col = (t & 15) * 4;

    float4 avr[2], bvr;
#pragma unroll
    for (int half_ = 0; half_ < 2; half_++) {
        int r = a_row + half_ * 64;
        avr[half_] = make_float4(0.f, 0.f, 0.f, 0.f);
        if (bm + r < M) avr[half_] = *(const float4*)&A[(size_t)(bm + r) * K + a_col];
    }
    bvr = *(const float4*)&B[(size_t)b_row * N + bn + b_col];

    for (int k0 = 0; k0 < K; k0 += GBK) {
#pragma unroll
        for (int half_ = 0; half_ < 2; half_++) {
            int r = a_row + half_ * 64;
            uint4 u;
            u.x = f2tf32(avr[half_].x); u.y = f2tf32(avr[half_].y);
            u.z = f2tf32(avr[half_].z); u.w = f2tf32(avr[half_].w);
            *(uint4*)&As[r][a_col] = u;
        }
        {
            uint4 u;
            u.x = f2tf32(bvr.x); u.y = f2tf32(bvr.y);
            u.z = f2tf32(bvr.z); u.w = f2tf32(bvr.w);
            *(uint4*)&Bs[b_row][b_col] = u;
        }
        __syncthreads();

        int kn = k0 + GBK;
        if (kn < K) {
#pragma unroll
            for (int half_ = 0; half_ < 2; half_++) {
                int r = a_row + half_ * 64;
                avr[half_] = make_float4(0.f, 0.f, 0.f, 0.f);
                if (bm + r < M) avr[half_] = *(const float4*)&A[(size_t)(bm + r) * K + kn + a_col];
            }
            bvr = *(const float4*)&B[(size_t)(kn + b_row) * N + bn + b_col];
        }

#pragma unroll
        for (int ks = 0; ks < GBK; ks += 8) {
            unsigned af[2][4], bf[4][2];
#pragma unroll
            for (int mt = 0; mt < 2; mt++) {
                int r = wm + mt * 16 + lr;
                int c = ks + lc;
                af[mt][0] = As[r][c];
                af[mt][1] = As[r + 8][c];
                af[mt][2] = As[r][c + 4];
                af[mt][3] = As[r + 8][c + 4];
            }
#pragma unroll
            for (int nt = 0; nt < 4; nt++) {
                int cc = wn + nt * 8 + lr;
                int kk = ks + lc;
                bf[nt][0] = Bs[kk][cc];
                bf[nt][1] = Bs[kk + 4][cc];
            }
#pragma unroll
            for (int mt = 0; mt < 2; mt++)
#pragma unroll
                for (int nt = 0; nt < 4; nt++)
                    mma_tf32(acc[mt][nt], af[mt][0], af[mt][1], af[mt][2], af[mt][3],
                             bf[nt][0], bf[nt][1]);
        }
        __syncthreads();
    }

#pragma unroll
    for (int mt = 0; mt < 2; mt++) {
#pragma unroll
        for (int nt = 0; nt < 4; nt++) {
            int r0 = bm + wm + mt * 16 + lr;
            int cc = bn + wn + nt * 8 + 2 * lc;
            if (r0 < M)
                *(__half2*)&C[(size_t)r0 * N + cc] = __floats2half2_rn(acc[mt][nt][0], acc[mt][nt][1]);
            if (r0 + 8 < M)
                *(__half2*)&C[(size_t)(r0 + 8) * N + cc] = __floats2half2_rn(acc[mt][nt][2], acc[mt][nt][3]);
        }
    }
}

// ---- GEMM B: 64x64 tile, 128 threads (4 warps 2x2), half A, half C ----
__global__ __launch_bounds__(128) void gemm64_tf32_kernel(
    const __half* __restrict__ A, const float* __restrict__ B,
    __half* __restrict__ C, int M, int N, int K) {
    __shared__ unsigned As[64][ASTRIDE];
    __shared__ unsigned Bs[GBK][BSTRIDE];

    int t = threadIdx.x;
    int lane = t & 31;
    int warp = t >> 5;
    int wm = (warp >> 1) * 32;
    int wn = (warp & 1) * 32;
    int bm = blockIdx.y * 64;
    int bn = blockIdx.x * GBN;

    int lr = lane >> 2;
    int lc = lane & 3;

    float acc[2][4][4];
#pragma unroll
    for (int mt = 0; mt < 2; mt++)
#pragma unroll
        for (int nt = 0; nt < 4; nt++)
#pragma unroll
            for (int i = 0; i < 4; i++) acc[mt][nt][i] = 0.f;

    int a_row = t >> 2;
    int a_col = (t & 3) * 4;
    int b_row = t >> 4;
    int b_col = (t & 15) * 4;

    float4 avr[2], bvr[2];
#pragma unroll
    for (int half_ = 0; half_ < 2; half_++) {
        int r = a_row + half_ * 32;
        avr[half_] = make_float4(0.f, 0.f, 0.f, 0.f);
        if (bm + r < M) {
            uint2 u = *(const uint2*)&A[(size_t)(bm + r) * K + a_col];
            float2 f0 = __half22float2(*(__half2*)&u.x);
            float2 f1 = __half22float2(*(__half2*)&u.y);
            avr[half_] = make_float4(f0.x, f0.y, f1.x, f1.y);
        }
        bvr[half_] = *(const float4*)&B[(size_t)(b_row + half_ * 8) * N + bn + b_col];
    }

    for (int k0 = 0; k0 < K; k0 += GBK) {
#pragma unroll
        for (int half_ = 0; half_ < 2; half_++) {
            int r = a_row + half_ * 32;
            uint4 u;
            u.x = f2tf32(avr[half_].x); u.y = f2tf32(avr[half_].y);
            u.z = f2tf32(avr[half_].z); u.w = f2tf32(avr[half_].w);
            *(uint4*)&As[r][a_col] = u;
            uint4 v;
            v.x = f2tf32(bvr[half_].x); v.y = f2tf32(bvr[half_].y);
            v.z = f2tf32(bvr[half_].z); v.w = f2tf32(bvr[half_].w);
            *(uint4*)&Bs[b_row + half_ * 8][b_col] = v;
        }
        __syncthreads();

        int kn = k0 + GBK;
        if (kn < K) {
#pragma unroll
            for (int half_ = 0; half_ < 2; half_++) {
                int r = a_row + half_ * 32;
                avr[half_] = make_float4(0.f, 0.f, 0.f, 0.f);
                if (bm + r < M) {
                    uint2 u = *(const uint2*)&A[(size_t)(bm + r) * K + kn + a_col];
                    float2 f0 = __half22float2(*(__half2*)&u.x);
                    float2 f1 = __half22float2(*(__half2*)&u.y);
                    avr[half_] = make_float4(f0.x, f0.y, f1.x, f1.y);
                }
                bvr[half_] = *(const float4*)&B[(size_t)(kn + b_row + half_ * 8) * N + bn + b_col];
            }
        }

#pragma unroll
        for (int ks = 0; ks < GBK; ks += 8) {
            unsigned af[2][4], bf[4][2];
#pragma unroll
            for (int mt = 0; mt < 2; mt++) {
                int r = wm + mt * 16 + lr;
                int c = ks + lc;
                af[mt][0] = As[r][c];
                af[mt][1] = As[r + 8][c];
                af[mt][2] = As[r][c + 4];
                af[mt][3] = As[r + 8][c + 4];
            }
#pragma unroll
            for (int nt = 0; nt < 4; nt++) {
                int cc = wn + nt * 8 + lr;
                int kk = ks + lc;
                bf[nt][0] = Bs[kk][cc];
                bf[nt][1] = Bs[kk + 4][cc];
            }
#pragma unroll
            for (int mt = 0; mt < 2; mt++)
#pragma unroll
                for (int nt = 0; nt < 4; nt++)
                    mma_tf32(acc[mt][nt], af[mt][0], af[mt][1], af[mt][2], af[mt][3],
                             bf[nt][0], bf[nt][1]);
        }
        __syncthreads();
    }

#pragma unroll
    for (int mt = 0; mt < 2; mt++) {
#pragma unroll
        for (int nt = 0; nt < 4; nt++) {
            int r0 = bm + wm + mt * 16 + lr;
            int cc = bn + wn + nt * 8 + 2 * lc;
            if (r0 < M)
                *(__half2*)&C[(size_t)r0 * N + cc] = __floats2half2_rn(acc[mt][nt][0], acc[mt][nt][1]);
            if (r0 + 8 < M)
                *(__half2*)&C[(size_t)(r0 + 8) * N + cc] = __floats2half2_rn(acc[mt][nt][2], acc[mt][nt][3]);
        }
    }
}

// ========================= GAT layer 1 =========================
// R14 structure + __launch_bounds__(256,5): cap regs at 51 -> 5 blocks/SM
// (40 warps, was 32). Edge-index pair loaded as one aligned int2.
__global__ __launch_bounds__(256, 5) void gat1_kernel() {
    int n = blockIdx.x * 8 + (threadIdx.x >> 5);
    if (n >= N_NODES) return;
    int lane = threadIdx.x & 31;

    int base = n * F1 + lane * 8;
    ull q[4];
    h8_to_p4(*(const uint4*)&g_ft1h[base], q);

    int deg = g_cursor[n];
    if (deg > MAXDEG) deg = MAXDEG;
    int eb = n * MAXDEG;

    float den = 0.f;
    ull acc[4] = {0ull, 0ull, 0ull, 0ull};

    int i = 0;
    for (; i + 2 <= deg; i += 2) {
        int2 sv = *(const int2*)&g_pad[eb + i];   // eb%64==0, i even -> aligned
        int s0 = sv.x, s1 = sv.y;
        ull k0[4], k1[4];
        h8_to_p4(*(const uint4*)&g_ft1h[s0 * F1 + lane * 8], k0);
        h8_to_p4(*(const uint4*)&g_ft1h[s1 * F1 + lane * 8], k1);
        float p0 = f2x_dot8(q, k0);
        float p1 = f2x_dot8(q, k1);
#pragma unroll
        for (int o = 1; o < 8; o <<= 1) {
            p0 += __shfl_xor_sync(0xffffffffu, p0, o);
            p1 += __shfl_xor_sync(0xffffffffu, p1, o);
        }
        float w0 = __expf(p0 * 0.125f);
        float w1 = __expf(p1 * 0.125f);
        den += w0 + w1;
        ull w0p = f2x_pack(w0, w0);
        ull w1p = f2x_pack(w1, w1);
#pragma unroll
        for (int j = 0; j < 4; j++)
            acc[j] = f2x_fma(w1p, k1[j], f2x_fma(w0p, k0[j], acc[j]));
    }
    if (i < deg) {
        int s0 = g_pad[eb + i];
        ull k0[4];
        h8_to_p4(*(const uint4*)&g_ft1h[s0 * F1 + lane * 8], k0);
        float p0 = f2x_dot8(q, k0);
#pragma unroll
        for (int o = 1; o < 8; o <<= 1) p0 += __shfl_xor_sync(0xffffffffu, p0, o);
        float w0 = __expf(p0 * 0.125f);
        den += w0;
        ull w0p = f2x_pack(w0, w0);
#pragma unroll
        for (int j = 0; j < 4; j++) acc[j] = f2x_fma(w0p, k0[j], acc[j]);
    }

    float inv = (deg > 0) ? 1.f / den : 0.f;
    uint4 outw;
    __half2* op = (__half2*)&outw;
#pragma unroll
    for (int j = 0; j < 4; j++) {
        float2 t = f2x_unpack(acc[j]);
        op[j] = __floats2half2_rn(fmaxf(t.x * inv, 0.f), fmaxf(t.y * inv, 0.f));
    }
    *(uint4*)&g_x1h[base] = outw;
}

// ========================= GAT layer 2 =========================
__global__ __launch_bounds__(256, 5) void gat2_kernel(const int* __restrict__ gid) {
    int n = blockIdx.x * 8 + (threadIdx.x >> 5);
    if (n >= N_NODES) return;
    int lane = threadIdx.x & 31;
    int grp  = lane >> 3;
    int wl   = lane & 7;
    unsigned gmask = 0xFFu << (grp * 8);

    int base = n * HID + wl * 8;
    ull q[4];
    h8_to_p4(*(const uint4*)&g_ft2h[base], q);

    int deg = g_cursor[n];
    if (deg > MAXDEG) deg = MAXDEG;
    int eb = n * MAXDEG;

    float den = 0.f;
    ull acc[4] = {0ull, 0ull, 0ull, 0ull};

    for (int i = grp; i < deg; i += 4) {
        int s = g_pad[eb + i];
        ull k[4];
        h8_to_p4(*(const uint4*)&g_ft2h[s * HID + wl * 8], k);
        float p = f2x_dot8(q, k);
#pragma unroll
        for (int o = 1; o < 8; o <<= 1) p += __shfl_xor_sync(gmask, p, o);
        float w = __expf(p * 0.125f);
        den += w;
        ull wp = f2x_pack(w, w);
#pragma unroll
        for (int j = 0; j < 4; j++) acc[j] = f2x_fma(wp, k[j], acc[j]);
    }

    float a8[8];
#pragma unroll
    for (int j = 0; j < 4; j++) {
        float2 t = f2x_unpack(acc[j]);
        a8[2 * j] = t.x; a8[2 * j + 1] = t.y;
    }
#pragma unroll
    for (int o = 8; o <= 16; o <<= 1) {
        den += __shfl_xor_sync(0xffffffffu, den, o);
#pragma unroll
        for (int j = 0; j < 8; j++)
            a8[j] += __shfl_xor_sync(0xffffffffu, a8[j], o);
    }

    float inv = (deg > 0) ? 1.f / den : 0.f;
    int g = gid[n];
    if (grp == 0) {
#pragma unroll
        for (int j = 0; j < 8; j++)
            atomicAdd(&g_pool[g * HID + wl * 8 + j], fmaxf(a8[j] * inv, 0.f));
        if (wl == 0) atomicAdd(&g_pcnt[g], 1.f);
    }
}

// ---- classifier ----
__global__ void final_kernel(const float* __restrict__ Wc, const float* __restrict__ bc,
                             float* __restrict__ out) {
    int g = blockIdx.x;
    int t = threadIdx.x;
    __shared__ float p[HID];
    float cnt = g_pcnt[g];
    float inv = (cnt > 0.f) ? 1.f / cnt : 0.f;
    p[t] = g_pool[g * HID + t] * inv;
    __syncthreads();
    if (t < N_CLASSES) {
        float s = bc[t];
#pragma unroll
        for (int d = 0; d < HID; d++) s += p[d] * Wc[d * N_CLASSES + t];
        out[g * N_CLASSES + t] = s;
    }
}

extern "C" void kernel_launch(void* const* d_in, const int* in_sizes, int n_in,
                              void* d_out, int out_size) {
    const float* h   = (const float*)d_in[0];
    const int*   src = (const int*)d_in[1];
    const int*   dst = (const int*)d_in[2];
    const int*   gid = (const int*)d_in[3];
    const float* W1  = (const float*)d_in[4];
    const float* W2  = (const float*)d_in[5];
    const float* Wc  = (const float*)d_in[6];
    const float* bc  = (const float*)d_in[7];
    float* out = (float*)d_out;
    (void)in_sizes; (void)n_in; (void)out_size;

    __half *ft1h, *x1h, *ft2h;
    cudaGetSymbolAddress((void**)&ft1h, g_ft1h);
    cudaGetSymbolAddress((void**)&x1h,  g_x1h);
    cudaGetSymbolAddress((void**)&ft2h, g_ft2h);

    zero_kernel<<<(N_NODES + 255) / 256, 256>>>();
    scatter_kernel<<<(N_EDGES / 4 + 255) / 256, 256>>>(src, dst);

    {
        dim3 grid(F1 / GBN, (N_NODES + GBM - 1) / GBM);
        gemm_tf32_kernel<<<grid, 256>>>(h, W1, ft1h, N_NODES, F1, IN_DIM);
    }
    gat1_kernel<<<(N_NODES + 7) / 8, 256>>>();

    {
        dim3 grid(HID / GBN, (N_NODES + 63) / 64);
        gemm64_tf32_kernel<<<grid, 128>>>(x1h, W2, ft2h, N_NODES, HID, F1);
    }
    gat2_kernel<<<(N_NODES + 7) / 8, 256>>>(gid);

    final_kernel<<<NUM_GRAPHS, 64>>>(Wc, bc, out);
}

// round 16
// speedup vs baseline: 1.0612x; 1.0612x over previous
#include <cuda_runtime.h>
#include <cuda_fp16.h>
#include <math.h>

#define N_NODES   20000
#define N_EDGES   320000
#define IN_DIM    128
#define HID       64
#define HEADS     4
#define NUM_GRAPHS 128
#define N_CLASSES 10
#define F1        (HID*HEADS)   // 256
#define MAXDEG    64

typedef unsigned long long ull;

// ---- scratch (zero-initialized at module load; kernels self-clean) ----
__device__ __half g_ft1h[N_NODES * F1];
__device__ __half g_x1h [N_NODES * F1];
__device__ __half g_ft2h[N_NODES * HID];
__device__ int    g_cursor[N_NODES];
__device__ int    g_pad[N_NODES * MAXDEG];
__device__ float  g_pool[NUM_GRAPHS * HID];
__device__ float  g_pcnt[NUM_GRAPHS];

// ---- packed f32x2 helpers ----
__device__ __forceinline__ ull f2x_mul(ull a, ull b) {
    ull r; asm("mul.rn.f32x2 %0, %1, %2;" : "=l"(r) : "l"(a), "l"(b)); return r;
}
__device__ __forceinline__ ull f2x_fma(ull a, ull b, ull c) {
    ull r; asm("fma.rn.f32x2 %0, %1, %2, %3;" : "=l"(r) : "l"(a), "l"(b), "l"(c)); return r;
}
__device__ __forceinline__ ull f2x_pack(float lo, float hi) {
    ull r; asm("mov.b64 %0, {%1, %2};" : "=l"(r) : "f"(lo), "f"(hi)); return r;
}
__device__ __forceinline__ float2 f2x_unpack(ull v) {
    float2 t; asm("mov.b64 {%0, %1}, %2;" : "=f"(t.x), "=f"(t.y) : "l"(v)); return t;
}
__device__ __forceinline__ float f2x_dot8(const ull* a, const ull* b) {
    ull s = f2x_mul(a[0], b[0]);
    s = f2x_fma(a[1], b[1], s);
    s = f2x_fma(a[2], b[2], s);
    s = f2x_fma(a[3], b[3], s);
    float2 t = f2x_unpack(s);
    return t.x + t.y;
}
__device__ __forceinline__ void h8_to_p4(uint4 raw, ull* p) {
    __half2* hp = (__half2*)&raw;
#pragma unroll
    for (int j = 0; j < 4; j++) {
        float2 t = __half22float2(hp[j]);
        p[j] = f2x_pack(t.x, t.y);
    }
}

// ========================= TF32 GEMM helpers =========================
__device__ __forceinline__ unsigned f2tf32(float x) {
    unsigned r;
    asm("cvt.rna.tf32.f32 %0, %1;" : "=r"(r) : "f"(x));
    return r;
}

__device__ __forceinline__ void mma_tf32(float c[4],
                                         unsigned a0, unsigned a1, unsigned a2, unsigned a3,
                                         unsigned b0, unsigned b1) {
    asm volatile(
        "mma.sync.aligned.m16n8k8.row.col.f32.tf32.tf32.f32 "
        "{%0,%1,%2,%3}, {%4,%5,%6,%7}, {%8,%9}, {%0,%1,%2,%3};\n"
        : "+f"(c[0]), "+f"(c[1]), "+f"(c[2]), "+f"(c[3])
        : "r"(a0), "r"(a1), "r"(a2), "r"(a3), "r"(b0), "r"(b1));
}

#define GBM 128
#define GBN 64
#define GBK 16
#define ASTRIDE 20
#define BSTRIDE 72

#define NSCAT ((N_EDGES / 4 + 255) / 256)            // 313 scatter blocks
#define GEMM1_BX (F1 / GBN)                          // 4
#define GEMM1_BY ((N_NODES + GBM - 1) / GBM)         // 157

// ---- FUSED: scatter (blocks [0,NSCAT)) + layer-1 GEMM (rest) ----
// Independent work: scatter writes g_cursor/g_pad; GEMM reads h/W1 -> g_ft1h.
__global__ __launch_bounds__(256) void scatter_gemm1_kernel(
    const int* __restrict__ src, const int* __restrict__ dst,
    const float* __restrict__ A, const float* __restrict__ B,
    __half* __restrict__ C, int M, int N, int K) {
    __shared__ unsigned As[GBM][ASTRIDE];
    __shared__ unsigned Bs[GBK][BSTRIDE];

    if (blockIdx.x < NSCAT) {
        // ---------------- scatter role ----------------
        int i = blockIdx.x * blockDim.x + threadIdx.x;
        if (i < N_EDGES / 4) {
            int4 d = ((const int4*)dst)[i];
            int4 s = ((const int4*)src)[i];
            int p0 = atomicAdd(&g_cursor[d.x], 1);
            int p1 = atomicAdd(&g_cursor[d.y], 1);
            int p2 = atomicAdd(&g_cursor[d.z], 1);
            int p3 = atomicAdd(&g_cursor[d.w], 1);
            if (p0 < MAXDEG) g_pad[d.x * MAXDEG + p0] = s.x;
            if (p1 < MAXDEG) g_pad[d.y * MAXDEG + p1] = s.y;
            if (p2 < MAXDEG) g_pad[d.z * MAXDEG + p2] = s.z;
            if (p3 < MAXDEG) g_pad[d.w * MAXDEG + p3] = s.w;
        }
        return;
    }

    // ---------------- GEMM role (128x64 tile) ----------------
    int bid = blockIdx.x - NSCAT;
    int bx = bid % GEMM1_BX;
    int by = bid / GEMM1_BX;

    int t = threadIdx.x;
    int lane = t & 31;
    int warp = t >> 5;
    int wm = (warp >> 1) * 32;
    int wn = (warp & 1) * 32;
    int bm = by * GBM;
    int bn = bx * GBN;

    int lr = lane >> 2;
    int lc = lane & 3;

    float acc[2][4][4];
#pragma unroll
    for (int mt = 0; mt < 2; mt++)
#pragma unroll
        for (int nt = 0; nt < 4; nt++)
#pragma unroll
            for (int i = 0; i < 4; i++) acc[mt][nt][i] = 0.f;

    int a_row = t >> 2;
    int a_col = (t & 3) * 4;
    int b_row = t >> 4;
    int b_col = (t & 15) * 4;

    float4 avr[2], bvr;
#pragma unroll
    for (int half_ = 0; half_ < 2; half_++) {
        int r = a_row + half_ * 64;
        avr[half_] = make_float4(0.f, 0.f, 0.f, 0.f);
        if (bm + r < M) avr[half_] = *(const float4*)&A[(size_t)(bm + r) * K + a_col];
    }
    bvr = *(const float4*)&B[(size_t)b_row * N + bn + b_col];

    for (int k0 = 0; k0 < K; k0 += GBK) {
#pragma unroll
        for (int half_ = 0; half_ < 2; half_++) {
            int r = a_row + half_ * 64;
            uint4 u;
            u.x = f2tf32(avr[half_].x); u.y = f2tf32(avr[half_].y);
            u.z = f2tf32(avr[half_].z); u.w = f2tf32(avr[half_].w);
            *(uint4*)&As[r][a_col] = u;
        }
        {
            uint4 u;
            u.x = f2tf32(bvr.x); u.y = f2tf32(bvr.y);
            u.z = f2tf32(bvr.z); u.w = f2tf32(bvr.w);
            *(uint4*)&Bs[b_row][b_col] = u;
        }
        __syncthreads();

        int kn = k0 + GBK;
        if (kn < K) {
#pragma unroll
            for (int half_ = 0; half_ < 2; half_++) {
                int r = a_row + half_ * 64;
                avr[half_] = make_float4(0.f, 0.f, 0.f, 0.f);
                if (bm + r < M) avr[half_] = *(const float4*)&A[(size_t)(bm + r) * K + kn + a_col];
            }
            bvr = *(const float4*)&B[(size_t)(kn + b_row) * N + bn + b_col];
        }

#pragma unroll
        for (int ks = 0; ks < GBK; ks += 8) {
            unsigned af[2][4], bf[4][2];
#pragma unroll
            for (int mt = 0; mt < 2; mt++) {
                int r = wm + mt * 16 + lr;
                int c = ks + lc;
                af[mt][0] = As[r][c];
                af[mt][1] = As[r + 8][c];
                af[mt][2] = As[r][c + 4];
                af[mt][3] = As[r + 8][c + 4];
            }
#pragma unroll
            for (int nt = 0; nt < 4; nt++) {
                int cc = wn + nt * 8 + lr;
                int kk = ks + lc;
                bf[nt][0] = Bs[kk][cc];
                bf[nt][1] = Bs[kk + 4][cc];
            }
#pragma unroll
            for (int mt = 0; mt < 2; mt++)
#pragma unroll
                for (int nt = 0; nt < 4; nt++)
                    mma_tf32(acc[mt][nt], af[mt][0], af[mt][1], af[mt][2], af[mt][3],
                             bf[nt][0], bf[nt][1]);
        }
        __syncthreads();
    }

#pragma unroll
    for (int mt = 0; mt < 2; mt++) {
#pragma unroll
        for (int nt = 0; nt < 4; nt++) {
            int r0 = bm + wm + mt * 16 + lr;
            int cc = bn + wn + nt * 8 + 2 * lc;
            if (r0 < M)
                *(__half2*)&C[(size_t)r0 * N + cc] = __floats2half2_rn(acc[mt][nt][0], acc[mt][nt][1]);
            if (r0 + 8 < M)
                *(__half2*)&C[(size_t)(r0 + 8) * N + cc] = __floats2half2_rn(acc[mt][nt][2], acc[mt][nt][3]);
        }
    }
}

// ---- GEMM B: 64x64 tile, 128 threads (4 warps 2x2), half A, half C ----
__global__ __launch_bounds__(128) void gemm64_tf32_kernel(
    const __half* __restrict__ A, const float* __restrict__ B,
    __half* __restrict__ C, int M, int N, int K) {
    __shared__ unsigned As[64][ASTRIDE];
    __shared__ unsigned Bs[GBK][BSTRIDE];

    int t = threadIdx.x;
    int lane = t & 31;
    int warp = t >> 5;
    int wm = (warp >> 1) * 32;
    int wn = (warp & 1) * 32;
    int bm = blockIdx.y * 64;
    int bn = blockIdx.x * GBN;

    int lr = lane >> 2;
    int lc = lane & 3;

    float acc[2][4][4];
#pragma unroll
    for (int mt = 0; mt < 2; mt++)
#pragma unroll
        for (int nt = 0; nt < 4; nt++)
#pragma unroll
            for (int i = 0; i < 4; i++) acc[mt][nt][i] = 0.f;

    int a_row = t >> 2;
    int a_col = (t & 3) * 4;
    int b_row = t >> 4;
    int b_col = (t & 15) * 4;

    float4 avr[2], bvr[2];
#pragma unroll
    for (int half_ = 0; half_ < 2; half_++) {
        int r = a_row + half_ * 32;
        avr[half_] = make_float4(0.f, 0.f, 0.f, 0.f);
        if (bm + r < M) {
            uint2 u = *(const uint2*)&A[(size_t)(bm + r) * K + a_col];
            float2 f0 = __half22float2(*(__half2*)&u.x);
            float2 f1 = __half22float2(*(__half2*)&u.y);
            avr[half_] = make_float4(f0.x, f0.y, f1.x, f1.y);
        }
        bvr[half_] = *(const float4*)&B[(size_t)(b_row + half_ * 8) * N + bn + b_col];
    }

    for (int k0 = 0; k0 < K; k0 += GBK) {
#pragma unroll
        for (int half_ = 0; half_ < 2; half_++) {
            int r = a_row + half_ * 32;
            uint4 u;
            u.x = f2tf32(avr[half_].x); u.y = f2tf32(avr[half_].y);
            u.z = f2tf32(avr[half_].z); u.w = f2tf32(avr[half_].w);
            *(uint4*)&As[r][a_col] = u;
            uint4 v;
            v.x = f2tf32(bvr[half_].x); v.y = f2tf32(bvr[half_].y);
            v.z = f2tf32(bvr[half_].z); v.w = f2tf32(bvr[half_].w);
            *(uint4*)&Bs[b_row + half_ * 8][b_col] = v;
        }
        __syncthreads();

        int kn = k0 + GBK;
        if (kn < K) {
#pragma unroll
            for (int half_ = 0; half_ < 2; half_++) {
                int r = a_row + half_ * 32;
                avr[half_] = make_float4(0.f, 0.f, 0.f, 0.f);
                if (bm + r < M) {
                    uint2 u = *(const uint2*)&A[(size_t)(bm + r) * K + kn + a_col];
                    float2 f0 = __half22float2(*(__half2*)&u.x);
                    float2 f1 = __half22float2(*(__half2*)&u.y);
                    avr[half_] = make_float4(f0.x, f0.y, f1.x, f1.y);
                }
                bvr[half_] = *(const float4*)&B[(size_t)(kn + b_row + half_ * 8) * N + bn + b_col];
            }
        }

#pragma unroll
        for (int ks = 0; ks < GBK; ks += 8) {
            unsigned af[2][4], bf[4][2];
#pragma unroll
            for (int mt = 0; mt < 2; mt++) {
                int r = wm + mt * 16 + lr;
                int c = ks + lc;
                af[mt][0] = As[r][c];
                af[mt][1] = As[r + 8][c];
                af[mt][2] = As[r][c + 4];
                af[mt][3] = As[r + 8][c + 4];
            }
#pragma unroll
            for (int nt = 0; nt < 4; nt++) {
                int cc = wn + nt * 8 + lr;
                int kk = ks + lc;
                bf[nt][0] = Bs[kk][cc];
                bf[nt][1] = Bs[kk + 4][cc];
            }
#pragma unroll
            for (int mt = 0; mt < 2; mt++)
#pragma unroll
                for (int nt = 0; nt < 4; nt++)
                    mma_tf32(acc[mt][nt], af[mt][0], af[mt][1], af[mt][2], af[mt][3],
                             bf[nt][0], bf[nt][1]);
        }
        __syncthreads();
    }

#pragma unroll
    for (int mt = 0; mt < 2; mt++) {
#pragma unroll
        for (int nt = 0; nt < 4; nt++) {
            int r0 = bm + wm + mt * 16 + lr;
            int cc = bn + wn + nt * 8 + 2 * lc;
            if (r0 < M)
                *(__half2*)&C[(size_t)r0 * N + cc] = __floats2half2_rn(acc[mt][nt][0], acc[mt][nt][1]);
            if (r0 + 8 < M)
                *(__half2*)&C[(size_t)(r0 + 8) * N + cc] = __floats2half2_rn(acc[mt][nt][2], acc[mt][nt][3]);
        }
    }
}

// ========================= GAT layer 1 (R14 exact) =========================
__global__ __launch_bounds__(256) void gat1_kernel() {
    int n = blockIdx.x * 8 + (threadIdx.x >> 5);
    if (n >= N_NODES) return;
    int lane = threadIdx.x & 31;

    int base = n * F1 + lane * 8;
    ull q[4];
    h8_to_p4(*(const uint4*)&g_ft1h[base], q);

    int deg = g_cursor[n];
    if (deg > MAXDEG) deg = MAXDEG;
    int eb = n * MAXDEG;

    float den = 0.f;
    ull acc[4] = {0ull, 0ull, 0ull, 0ull};

    int i = 0;
    for (; i + 2 <= deg; i += 2) {
        int2 sv = *(const int2*)&g_pad[eb + i];
        int s0 = sv.x, s1 = sv.y;
        ull k0[4], k1[4];
        h8_to_p4(*(const uint4*)&g_ft1h[s0 * F1 + lane * 8], k0);
        h8_to_p4(*(const uint4*)&g_ft1h[s1 * F1 + lane * 8], k1);
        float p0 = f2x_dot8(q, k0);
        float p1 = f2x_dot8(q, k1);
#pragma unroll
        for (int o = 1; o < 8; o <<= 1) {
            p0 += __shfl_xor_sync(0xffffffffu, p0, o);
            p1 += __shfl_xor_sync(0xffffffffu, p1, o);
        }
        float w0 = __expf(p0 * 0.125f);
        float w1 = __expf(p1 * 0.125f);
        den += w0 + w1;
        ull w0p = f2x_pack(w0, w0);
        ull w1p = f2x_pack(w1, w1);
#pragma unroll
        for (int j = 0; j < 4; j++)
            acc[j] = f2x_fma(w1p, k1[j], f2x_fma(w0p, k0[j], acc[j]));
    }
    if (i < deg) {
        int s0 = g_pad[eb + i];
        ull k0[4];
        h8_to_p4(*(const uint4*)&g_ft1h[s0 * F1 + lane * 8], k0);
        float p0 = f2x_dot8(q, k0);
#pragma unroll
        for (int o = 1; o < 8; o <<= 1) p0 += __shfl_xor_sync(0xffffffffu, p0, o);
        float w0 = __expf(p0 * 0.125f);
        den += w0;
        ull w0p = f2x_pack(w0, w0);
#pragma unroll
        for (int j = 0; j < 4; j++) acc[j] = f2x_fma(w0p, k0[j], acc[j]);
    }

    float inv = (deg > 0) ? 1.f / den : 0.f;
    uint4 outw;
    __half2* op = (__half2*)&outw;
#pragma unroll
    for (int j = 0; j < 4; j++) {
        float2 t = f2x_unpack(acc[j]);
        op[j] = __floats2half2_rn(fmaxf(t.x * inv, 0.f), fmaxf(t.y * inv, 0.f));
    }
    *(uint4*)&g_x1h[base] = outw;
}

// ========================= GAT layer 2 (R14 + cursor self-clean) ==========
__global__ __launch_bounds__(256) void gat2_kernel(const int* __restrict__ gid) {
    int n = blockIdx.x * 8 + (threadIdx.x >> 5);
    if (n >= N_NODES) return;
    int lane = threadIdx.x & 31;
    int grp  = lane >> 3;
    int wl   = lane & 7;
    unsigned gmask = 0xFFu << (grp * 8);

    int base = n * HID + wl * 8;
    ull q[4];
    h8_to_p4(*(const uint4*)&g_ft2h[base], q);

    int deg = g_cursor[n];
    if (deg > MAXDEG) deg = MAXDEG;
    int eb = n * MAXDEG;

    float den = 0.f;
    ull acc[4] = {0ull, 0ull, 0ull, 0ull};

    for (int i = grp; i < deg; i += 4) {
        int s = g_pad[eb + i];
        ull k[4];
        h8_to_p4(*(const uint4*)&g_ft2h[s * HID + wl * 8], k);
        float p = f2x_dot8(q, k);
#pragma unroll
        for (int o = 1; o < 8; o <<= 1) p += __shfl_xor_sync(gmask, p, o);
        float w = __expf(p * 0.125f);
        den += w;
        ull wp = f2x_pack(w, w);
#pragma unroll
        for (int j = 0; j < 4; j++) acc[j] = f2x_fma(wp, k[j], acc[j]);
    }

    float a8[8];
#pragma unroll
    for (int j = 0; j < 4; j++) {
        float2 t = f2x_unpack(acc[j]);
        a8[2 * j] = t.x; a8[2 * j + 1] = t.y;
    }
#pragma unroll
    for (int o = 8; o <= 16; o <<= 1) {
        den += __shfl_xor_sync(0xffffffffu, den, o);
#pragma unroll
        for (int j = 0; j < 8; j++)
            a8[j] += __shfl_xor_sync(0xffffffffu, a8[j], o);
    }

    float inv = (deg > 0) ? 1.f / den : 0.f;
    int g = gid[n];
    if (grp == 0) {
#pragma unroll
        for (int j = 0; j < 8; j++)
            atomicAdd(&g_pool[g * HID + wl * 8 + j], fmaxf(a8[j] * inv, 0.f));
        if (wl == 0) {
            atomicAdd(&g_pcnt[g], 1.f);
            g_cursor[n] = 0;   // self-clean for next replay (last reader)
        }
    }
}

// ---- classifier (+ pool/pcnt self-clean) ----
__global__ void final_kernel(const float* __restrict__ Wc, const float* __restrict__ bc,
                             float* __restrict__ out) {
    int g = blockIdx.x;
    int t = threadIdx.x;
    __shared__ float p[HID];
    float cnt = g_pcnt[g];
    float inv = (cnt > 0.f) ? 1.f / cnt : 0.f;
    p[t] = g_pool[g * HID + t] * inv;
    g_pool[g * HID + t] = 0.f;         // self-clean
    if (t == 0) g_pcnt[g] = 0.f;       // self-clean
    __syncthreads();
    if (t < N_CLASSES) {
        float s = bc[t];
#pragma unroll
        for (int d = 0; d < HID; d++) s += p[d] * Wc[d * N_CLASSES + t];
        out[g * N_CLASSES + t] = s;
    }
}

extern "C" void kernel_launch(void* const* d_in, const int* in_sizes, int n_in,
                              void* d_out, int out_size) {
    const float* h   = (const float*)d_in[0];
    const int*   src = (const int*)d_in[1];
    const int*   dst = (const int*)d_in[2];
    const int*   gid = (const int*)d_in[3];
    const float* W1  = (const float*)d_in[4];
    const float* W2  = (const float*)d_in[5];
    const float* Wc  = (const float*)d_in[6];
    const float* bc  = (const float*)d_in[7];
    float* out = (float*)d_out;
    (void)in_sizes; (void)n_in; (void)out_size;

    __half *ft1h, *x1h, *ft2h;
    cudaGetSymbolAddress((void**)&ft1h, g_ft1h);
    cudaGetSymbolAddress((void**)&x1h,  g_x1h);
    cudaGetSymbolAddress((void**)&ft2h, g_ft2h);

    // fused scatter + gemm1 (independent roles in one launch)
    {
        int nblocks = NSCAT + GEMM1_BX * GEMM1_BY;
        scatter_gemm1_kernel<<<nblocks, 256>>>(src, dst, h, W1, ft1h,
                                               N_NODES, F1, IN_DIM);
    }
    gat1_kernel<<<(N_NODES + 7) / 8, 256>>>();

    {
        dim3 grid(HID / GBN, (N_NODES + 63) / 64);
        gemm64_tf32_kernel<<<grid, 128>>>(x1h, W2, ft2h, N_NODES, HID, F1);
    }
    gat2_kernel<<<(N_NODES + 7) / 8, 256>>>(gid);

    final_kernel<<<NUM_GRAPHS, 64>>>(Wc, bc, out);
}